// round 1
// baseline (speedup 1.0000x reference)
#include <cuda_runtime.h>
#include <math.h>

// Problem constants
#define NPART   65536
#define NSTEPS  50
#define HD      128     // hidden width
#define CTXD    128     // context dim
#define TED     32      // time embedding dim
#define THREADS 256
#define P_CTA   32      // particles per CTA
#define P_WARP  4       // particles per warp
#define NWARP   8
#define H1PAD   132     // padded row length for h1 transposed buffers (multiple of 4)

struct Smem {
    float wA[HD * HD];                       // W1ctx then W2        (64 KB)
    float wB[HD * HD];                       // V1ctx then V2        (64 KB)
    float pc1[P_CTA * HD];                   // ctx@W1ctx + b1       (16 KB) (emb scratch early)
    float cc1[P_CTA * HD];                   // ctx@V1ctx + c1       (16 KB)
    float h1T[NWARP][2][P_WARP * H1PAD];     // per-warp h1 for both nets (33 KB) (W1temb scratch early)
    float te_all[NSTEPS * HD];               // temb(t) @ W1temb     (25.6 KB)
    float w1z[2 * HD];                       // W1 rows 0,1
    float v1z[2 * HD];                       // V1 rows 0,1
    float v1t[HD];                           // V1 row 130 (time column)
    float zbuf[P_CTA * 2];
    float times_s[NSTEPS + 1];
    float dts[NSTEPS];
    float ss[NSTEPS];                        // noise scale per step
};

// Dual register-blocked matvec: acc[p][q] += h[p][k] * W[k][4*lane+q] for both nets.
__device__ __forceinline__ void matvec_dual(
    const float* __restrict__ hTa, const float* __restrict__ hTb,
    const float* __restrict__ wA,  const float* __restrict__ wB,
    int lane, float (&accA)[P_WARP][4], float (&accB)[P_WARP][4])
{
#pragma unroll
    for (int p = 0; p < P_WARP; p++)
#pragma unroll
        for (int q = 0; q < 4; q++) { accA[p][q] = 0.f; accB[p][q] = 0.f; }

#pragma unroll 4
    for (int k = 0; k < HD; k++) {
        float4 wa = *(const float4*)&wA[k * HD + 4 * lane];  // conflict-free LDS.128
        float4 wb = *(const float4*)&wB[k * HD + 4 * lane];
#pragma unroll
        for (int p = 0; p < P_WARP; p++) {
            float ha = hTa[p * H1PAD + k];   // warp-uniform broadcast LDS
            float hb = hTb[p * H1PAD + k];
            accA[p][0] = fmaf(ha, wa.x, accA[p][0]);
            accA[p][1] = fmaf(ha, wa.y, accA[p][1]);
            accA[p][2] = fmaf(ha, wa.z, accA[p][2]);
            accA[p][3] = fmaf(ha, wa.w, accA[p][3]);
            accB[p][0] = fmaf(hb, wb.x, accB[p][0]);
            accB[p][1] = fmaf(hb, wb.y, accB[p][1]);
            accB[p][2] = fmaf(hb, wb.z, accB[p][2]);
            accB[p][3] = fmaf(hb, wb.w, accB[p][3]);
        }
    }
}

__global__ void __launch_bounds__(THREADS, 1)
sde_kernel(const float* __restrict__ z0,
           const float* __restrict__ pctx,
           const float* __restrict__ cctx,
           const float* __restrict__ times,
           const float* __restrict__ xi,
           const float* __restrict__ freqs,
           const float* __restrict__ log_diff,
           const float* __restrict__ W1, const float* __restrict__ b1,
           const float* __restrict__ W2, const float* __restrict__ b2,
           const float* __restrict__ W3, const float* __restrict__ b3,
           const float* __restrict__ V1, const float* __restrict__ c1,
           const float* __restrict__ V2, const float* __restrict__ c2,
           const float* __restrict__ V3, const float* __restrict__ c3,
           float* __restrict__ traj)
{
    extern __shared__ float smraw[];
    Smem* sm = reinterpret_cast<Smem*>(smraw);

    const int tid   = threadIdx.x;
    const int wid   = tid >> 5;
    const int lane  = tid & 31;
    const int p0    = lane >> 3;   // this lane's particle (layer-1 work split)
    const int kg    = lane & 7;    // this lane's k-group (16 k values)
    const int nBase = blockIdx.x * P_CTA;
    const int nWarp = nBase + wid * P_WARP;

    // ---------------- prologue ----------------
    for (int i = tid; i <= NSTEPS; i += THREADS) sm->times_s[i] = times[i];
    float gb = log1pf(expf(log_diff[0]));   // softplus
    __syncthreads();
    if (tid < NSTEPS) {
        float t_i = sm->times_s[tid];
        float dt  = sm->times_s[tid + 1] - t_i;
        sm->dts[tid] = dt;
        sm->ss[tid]  = gb * (1.f - t_i) * sqrtf(fmaxf(dt, 1e-12f));
    }

    // W1temb rows (130..161) -> scratch in h1T region; emb table -> scratch in pc1 region
    float* wtmp = &sm->h1T[0][0][0];          // 4096 floats needed, region has 4224/warp*... plenty
    for (int i = tid; i < TED * HD; i += THREADS) wtmp[i] = W1[130 * HD + i];
    float* emb = sm->pc1;                     // NSTEPS*TED = 1600 floats
    for (int e = tid; e < NSTEPS * TED; e += THREADS) {
        int t = e / TED, i = e % TED;
        float arg = 6.2831853071795864769f * times[t] * freqs[i & 15];
        emb[e] = (i < 16) ? sinf(arg) : cosf(arg);
    }
    __syncthreads();

    // te_all[t][j] = emb(t) @ W1temb
    for (int e = tid; e < NSTEPS * HD; e += THREADS) {
        int t = e / HD, j = e % HD;
        float a = 0.f;
#pragma unroll
        for (int m = 0; m < TED; m++) a = fmaf(emb[t * TED + m], wtmp[m * HD + j], a);
        sm->te_all[e] = a;
    }
    __syncthreads();   // done with emb + wtmp scratch

    // ctx weight blocks: W1 rows 2..129 -> wA, V1 rows 2..129 -> wB
    for (int i = tid * 4; i < HD * HD; i += THREADS * 4) {
        *(float4*)&sm->wA[i] = *(const float4*)&W1[2 * HD + i];
        *(float4*)&sm->wB[i] = *(const float4*)&V1[2 * HD + i];
    }
    __syncthreads();

    // ---- one-time ctx projections: pc1 = pctx@W1ctx + b1, cc1 = cctx@V1ctx + c1 ----
    {
        float* hTa = sm->h1T[wid][0];
        float* hTb = sm->h1T[wid][1];
        const float* srcp = pctx + (size_t)nWarp * CTXD;
        const float* srcc = cctx + (size_t)nWarp * CTXD;
#pragma unroll
        for (int j = 0; j < 4; j++) {
            int k = kg * 16 + 4 * j;
            *(float4*)&hTa[p0 * H1PAD + k] = *(const float4*)&srcp[p0 * CTXD + k];
            *(float4*)&hTb[p0 * H1PAD + k] = *(const float4*)&srcc[p0 * CTXD + k];
        }
        __syncwarp();
        float accA[P_WARP][4], accB[P_WARP][4];
        matvec_dual(hTa, hTb, sm->wA, sm->wB, lane, accA, accB);
        float4 b1v = *(const float4*)&b1[4 * lane];
        float4 c1v = *(const float4*)&c1[4 * lane];
#pragma unroll
        for (int p = 0; p < P_WARP; p++) {
            float4 oa, ob;
            oa.x = accA[p][0] + b1v.x; oa.y = accA[p][1] + b1v.y;
            oa.z = accA[p][2] + b1v.z; oa.w = accA[p][3] + b1v.w;
            ob.x = accB[p][0] + c1v.x; ob.y = accB[p][1] + c1v.y;
            ob.z = accB[p][2] + c1v.z; ob.w = accB[p][3] + c1v.w;
            *(float4*)&sm->pc1[(wid * P_WARP + p) * HD + 4 * lane] = oa;
            *(float4*)&sm->cc1[(wid * P_WARP + p) * HD + 4 * lane] = ob;
        }
    }
    __syncthreads();   // everyone done reading wA/wB

    // step weights: W2 -> wA, V2 -> wB; small params
    for (int i = tid * 4; i < HD * HD; i += THREADS * 4) {
        *(float4*)&sm->wA[i] = *(const float4*)&W2[i];
        *(float4*)&sm->wB[i] = *(const float4*)&V2[i];
    }
    for (int i = tid; i < HD; i += THREADS) {
        sm->w1z[i]      = W1[i];
        sm->w1z[HD + i] = W1[HD + i];
        sm->v1z[i]      = V1[i];
        sm->v1z[HD + i] = V1[HD + i];
        sm->v1t[i]      = V1[130 * HD + i];
    }
    for (int i = tid; i < P_CTA * 2; i += THREADS) {
        float v = z0[(size_t)nBase * 2 + i];
        sm->zbuf[i] = v;
        traj[(size_t)nBase * 2 + i] = v;      // traj[0] = z0
    }

    // per-lane epilogue constants (registers, held across all steps)
    float4 b2v = *(const float4*)&b2[4 * lane];
    float4 c2v = *(const float4*)&c2[4 * lane];
    float b2a[4] = {b2v.x, b2v.y, b2v.z, b2v.w};
    float c2a[4] = {c2v.x, c2v.y, c2v.z, c2v.w};
    float w30[4], w31[4], v30[4], v31[4];
#pragma unroll
    for (int q = 0; q < 4; q++) {
        w30[q] = W3[(4 * lane + q) * 2 + 0];
        w31[q] = W3[(4 * lane + q) * 2 + 1];
        v30[q] = V3[(4 * lane + q) * 2 + 0];
        v31[q] = V3[(4 * lane + q) * 2 + 1];
    }
    float bc0 = (lane == 0) ? (b3[0] + c3[0]) : 0.f;
    float bc1 = (lane == 0) ? (b3[1] + c3[1]) : 0.f;
    __syncthreads();

    // ---------------- time-step loop (warp-synchronous only) ----------------
    float* hTa = sm->h1T[wid][0];
    float* hTb = sm->h1T[wid][1];
    const float* pcrow = &sm->pc1[(wid * P_WARP + p0) * HD];
    const float* ccrow = &sm->cc1[(wid * P_WARP + p0) * HD];

    for (int t = 0; t < NSTEPS; t++) {
        float t_i = sm->times_s[t];
        float dt  = sm->dts[t];
        float s   = sm->ss[t];
        float zp0 = sm->zbuf[(wid * P_WARP + p0) * 2 + 0];
        float zp1 = sm->zbuf[(wid * P_WARP + p0) * 2 + 1];

        // layer 1, both nets: h1 = relu(pc1 + z·W1z + te[t]) ; g1 = tanh(cc1 + z·V1z + t·V1t)
#pragma unroll
        for (int j = 0; j < 4; j++) {
            int k = kg * 16 + 4 * j;
            float4 pc = *(const float4*)&pcrow[k];
            float4 w0 = *(const float4*)&sm->w1z[k];
            float4 w1 = *(const float4*)&sm->w1z[HD + k];
            float4 te = *(const float4*)&sm->te_all[t * HD + k];
            float4 oa;
            oa.x = fmaxf(fmaf(zp1, w1.x, fmaf(zp0, w0.x, pc.x + te.x)), 0.f);
            oa.y = fmaxf(fmaf(zp1, w1.y, fmaf(zp0, w0.y, pc.y + te.y)), 0.f);
            oa.z = fmaxf(fmaf(zp1, w1.z, fmaf(zp0, w0.z, pc.z + te.z)), 0.f);
            oa.w = fmaxf(fmaf(zp1, w1.w, fmaf(zp0, w0.w, pc.w + te.w)), 0.f);
            *(float4*)&hTa[p0 * H1PAD + k] = oa;

            float4 cc = *(const float4*)&ccrow[k];
            float4 u0 = *(const float4*)&sm->v1z[k];
            float4 u1 = *(const float4*)&sm->v1z[HD + k];
            float4 vt = *(const float4*)&sm->v1t[k];
            float4 ob;
            ob.x = tanhf(fmaf(zp1, u1.x, fmaf(zp0, u0.x, fmaf(t_i, vt.x, cc.x))));
            ob.y = tanhf(fmaf(zp1, u1.y, fmaf(zp0, u0.y, fmaf(t_i, vt.y, cc.y))));
            ob.z = tanhf(fmaf(zp1, u1.z, fmaf(zp0, u0.z, fmaf(t_i, vt.z, cc.z))));
            ob.w = tanhf(fmaf(zp1, u1.w, fmaf(zp0, u0.w, fmaf(t_i, vt.w, cc.w))));
            *(float4*)&hTb[p0 * H1PAD + k] = ob;
        }
        __syncwarp();

        // layer 2 (both nets), fused layer-3 projection in epilogue
        float accA[P_WARP][4], accB[P_WARP][4];
        matvec_dual(hTa, hTb, sm->wA, sm->wB, lane, accA, accB);

        float d0[P_WARP], d1[P_WARP];
#pragma unroll
        for (int p = 0; p < P_WARP; p++) {
            float a0 = bc0, a1 = bc1;
#pragma unroll
            for (int q = 0; q < 4; q++) {
                float h2 = fmaxf(accA[p][q] + b2a[q], 0.f);
                a0 = fmaf(h2, w30[q], a0);
                a1 = fmaf(h2, w31[q], a1);
                float g2 = tanhf(accB[p][q] + c2a[q]);
                a0 = fmaf(g2, v30[q], a0);
                a1 = fmaf(g2, v31[q], a1);
            }
            d0[p] = a0; d1[p] = a1;
        }
        // warp reduce the 8 drift partials
#pragma unroll
        for (int off = 16; off > 0; off >>= 1) {
#pragma unroll
            for (int p = 0; p < P_WARP; p++) {
                d0[p] += __shfl_xor_sync(0xffffffffu, d0[p], off);
                d1[p] += __shfl_xor_sync(0xffffffffu, d1[p], off);
            }
        }

        // Euler + Euler-Maruyama update (lanes 0..3 own one particle each)
        if (lane < P_WARP) {
            int p = lane;
            int n = nWarp + p;
            float dd0 = (p == 0) ? d0[0] : (p == 1) ? d0[1] : (p == 2) ? d0[2] : d0[3];
            float dd1 = (p == 0) ? d1[0] : (p == 1) ? d1[1] : (p == 2) ? d1[2] : d1[3];
            float zz0 = sm->zbuf[(wid * P_WARP + p) * 2 + 0];
            float zz1 = sm->zbuf[(wid * P_WARP + p) * 2 + 1];
            float2 xv = *(const float2*)&xi[((size_t)t * NPART + n) * 2];
            float zn0 = fmaf(dd0, dt, zz0) + xv.x * s;
            float zn1 = fmaf(dd1, dt, zz1) + xv.y * s;
            sm->zbuf[(wid * P_WARP + p) * 2 + 0] = zn0;
            sm->zbuf[(wid * P_WARP + p) * 2 + 1] = zn1;
            *(float2*)&traj[((size_t)(t + 1) * NPART + n) * 2] = make_float2(zn0, zn1);
        }
        __syncwarp();
    }
}

extern "C" void kernel_launch(void* const* d_in, const int* in_sizes, int n_in,
                              void* d_out, int out_size)
{
    (void)in_sizes; (void)n_in; (void)out_size;
    const float* z0       = (const float*)d_in[0];
    const float* pctx     = (const float*)d_in[1];
    const float* cctx     = (const float*)d_in[2];
    const float* times    = (const float*)d_in[3];
    const float* xi       = (const float*)d_in[4];
    const float* freqs    = (const float*)d_in[5];
    const float* log_diff = (const float*)d_in[6];
    const float* W1 = (const float*)d_in[7];
    const float* b1 = (const float*)d_in[8];
    const float* W2 = (const float*)d_in[9];
    const float* b2 = (const float*)d_in[10];
    const float* W3 = (const float*)d_in[11];
    const float* b3 = (const float*)d_in[12];
    const float* V1 = (const float*)d_in[13];
    const float* c1 = (const float*)d_in[14];
    const float* V2 = (const float*)d_in[15];
    const float* c2 = (const float*)d_in[16];
    const float* V3 = (const float*)d_in[17];
    const float* c3 = (const float*)d_in[18];
    float* traj = (float*)d_out;

    cudaFuncSetAttribute(sde_kernel, cudaFuncAttributeMaxDynamicSharedMemorySize,
                         (int)sizeof(Smem));
    sde_kernel<<<NPART / P_CTA, THREADS, sizeof(Smem)>>>(
        z0, pctx, cctx, times, xi, freqs, log_diff,
        W1, b1, W2, b2, W3, b3, V1, c1, V2, c2, V3, c3, traj);
}